// round 1
// baseline (speedup 1.0000x reference)
#include <cuda_runtime.h>

#define Hh 112
#define Ww 112
#define NP (Hh*Ww)        // 12544 elements per plane
#define STR 113           // shared row stride (floats) — odd vs 32 banks
#define NCH 64
#define SMEM_BYTES (Hh*STR*4)   // 50624

// 5x5 depthwise conv over shared xp, 8 outputs per call.
// O0..O7 are the (compile-time) window start offsets for the 8 outputs,
// relative to the 12-float row segment loaded at 'rp'.
template<int O0,int O1,int O2,int O3,int O4,int O5,int O6,int O7>
__device__ __forceinline__ void conv8(const float* __restrict__ rp,
                                      const float* __restrict__ kc,
                                      float* __restrict__ acc)
{
#pragma unroll
    for (int r = 0; r < 5; r++) {
        float rv[12];
#pragma unroll
        for (int i = 0; i < 12; i++) rv[i] = rp[r*STR + i];
        const float* kr = kc + r*5;
        const int off[8] = {O0,O1,O2,O3,O4,O5,O6,O7};
#pragma unroll
        for (int j = 0; j < 8; j++) {
#pragma unroll
            for (int t = 0; t < 5; t++)
                acc[j] = fmaf(kr[t], rv[off[j] + t], acc[j]);
        }
    }
}

__global__ __launch_bounds__(256)
void bionorm_kernel(const float* __restrict__ x,
                    const float* __restrict__ sigma,
                    const float* __restrict__ pow_p,
                    const float* __restrict__ ker,
                    const float* __restrict__ weight,
                    const float* __restrict__ bias,
                    float* __restrict__ out)
{
    extern __shared__ float sh[];   // xp plane, [112][113]
    const int plane = blockIdx.x;          // b*C + c
    const int c = plane & (NCH - 1);
    const float* __restrict__ xin = x + (size_t)plane * NP;
    float* __restrict__ po = out + (size_t)plane * NP;

    const float p  = pow_p[c];
    const bool  p2 = (p == 2.0f);

    // ---- Phase 1: coalesced load + x^p into shared ----
    for (int i = threadIdx.x; i < NP/4; i += blockDim.x) {
        float4 v = reinterpret_cast<const float4*>(xin)[i];
        int base = i << 2;
        int y  = base / Ww;           // 112 | base%112 stays in one row (112%4==0)
        int xx = base - y * Ww;
        float4 r;
        if (p2) {
            r.x = v.x*v.x; r.y = v.y*v.y; r.z = v.z*v.z; r.w = v.w*v.w;
        } else {
            r.x = __powf(v.x, p); r.y = __powf(v.y, p);
            r.z = __powf(v.z, p); r.w = __powf(v.w, p);
        }
        float* d = &sh[y*STR + xx];
        d[0] = r.x; d[1] = r.y; d[2] = r.z; d[3] = r.w;
    }

    // per-channel params (uniform across block; L1/const-cached)
    float kc[25];
#pragma unroll
    for (int i = 0; i < 25; i++) kc[i] = __ldg(&ker[c*25 + i]);
    const float sgm = sigma[c];
    const float sp  = p2 ? sgm*sgm : __powf(sgm, p);
    const float wgt = weight[c];
    const float bs  = bias[c];

    __syncthreads();

    // ---- Phase 2: conv + normalize ----
    // 14 x-groups of 8 outputs, 112 rows. Lane mapping: consecutive threads
    // take consecutive y within an x-group -> shared reads stride 113
    // (bank shift 17, conflict-free; y-clamped duplicates are broadcasts).
    for (int idx = threadIdx.x; idx < 14*Hh; idx += blockDim.x) {
        int xg = idx / Hh;
        int y  = idx - xg*Hh;
        int x0 = xg << 3;
        int cy   = min(max(y, 2), 109);         // clamped conv center row
        int base = min(max(x0 - 2, 0), 100);    // 12-float segment start

        float acc[8];
#pragma unroll
        for (int j = 0; j < 8; j++) acc[j] = 0.0f;

        const float* rp = &sh[(cy - 2)*STR + base];
        if (xg == 0) {
            // outputs x=0..7, cx=clamp(x,2,109): offsets {0,0,0,1,2,3,4,5}
            conv8<0,0,0,1,2,3,4,5>(rp, kc, acc);
        } else if (xg == 13) {
            // outputs x=104..111: offsets {2,3,4,5,6,7,7,7}
            conv8<2,3,4,5,6,7,7,7>(rp, kc, acc);
        } else {
            conv8<0,1,2,3,4,5,6,7>(rp, kc, acc);
        }

        float* orow = po + y*Ww + x0;
#pragma unroll
        for (int j = 0; j < 8; j++) {
            float xpv = sh[y*STR + x0 + j];
            orow[j] = __fdividef(wgt * xpv, sp + acc[j]) + bs;
        }
    }
}

extern "C" void kernel_launch(void* const* d_in, const int* in_sizes, int n_in,
                              void* d_out, int out_size)
{
    const float* x      = (const float*)d_in[0];
    const float* sigma  = (const float*)d_in[1];
    const float* pow_p  = (const float*)d_in[2];
    const float* ker    = (const float*)d_in[3];
    const float* weight = (const float*)d_in[4];
    const float* bias   = (const float*)d_in[5];
    float* out = (float*)d_out;

    // >48KB dynamic shared requires opt-in (immediate API, capture-safe)
    cudaFuncSetAttribute(bionorm_kernel,
                         cudaFuncAttributeMaxDynamicSharedMemorySize,
                         SMEM_BYTES);

    bionorm_kernel<<<32*NCH, 256, SMEM_BYTES>>>(x, sigma, pow_p, ker,
                                                weight, bias, out);
}

// round 2
// speedup vs baseline: 1.4130x; 1.4130x over previous
#include <cuda_runtime.h>

#define Hh 112
#define Ww 112
#define NP (Hh*Ww)          // 12544 floats per plane
#define STR 113             // shared row stride (floats), odd vs 32 banks
#define NCH 64
#define SMEM_FLOATS 12672   // 112*113 + swizzle/pad
#define SMEM_BYTES (SMEM_FLOATS*4)

// swizzled shared address of (y, x):  y*113 + ((y>>5)&1) + x
__device__ __forceinline__ int saddr(int y, int x) {
    return y * STR + ((y >> 5) & 1) + x;
}

// 5x5 depthwise conv over shared xp for an 8-wide x 2-tall output tile.
// O0..O7: compile-time window-start offsets of the 8 outputs relative to the
// 12-float row segment starting at column 'bx'. Rows ybase..ybase+5 feed
// acc0 (kernel rows 0..4 on rows 0..4) and acc1 (rows 1..5). When two==false
// (replicate-pad makes both output rows identical) only acc0 is computed.
template<int O0,int O1,int O2,int O3,int O4,int O5,int O6,int O7>
__device__ __forceinline__ void conv8x2(const float* __restrict__ sh,
                                        int ybase, int bx,
                                        const float* __restrict__ kc,
                                        float* __restrict__ acc0,
                                        float* __restrict__ acc1,
                                        bool two)
{
    const int off[8] = {O0,O1,O2,O3,O4,O5,O6,O7};
#pragma unroll
    for (int rr = 0; rr < 6; rr++) {
        const int r = ybase + rr;
        const float* rp = sh + saddr(r, bx);
        float rv[12];
        if (rr < 5 || two) {
#pragma unroll
            for (int i = 0; i < 12; i++) rv[i] = rp[i];
        }
        if (rr < 5) {
            const float* kr = kc + rr * 5;
#pragma unroll
            for (int j = 0; j < 8; j++)
#pragma unroll
                for (int t = 0; t < 5; t++)
                    acc0[j] = fmaf(kr[t], rv[off[j] + t], acc0[j]);
        }
        if (rr >= 1 && two) {
            const float* kr = kc + (rr - 1) * 5;
#pragma unroll
            for (int j = 0; j < 8; j++)
#pragma unroll
                for (int t = 0; t < 5; t++)
                    acc1[j] = fmaf(kr[t], rv[off[j] + t], acc1[j]);
        }
    }
}

__global__ __launch_bounds__(256)
void bionorm_kernel(const float* __restrict__ x,
                    const float* __restrict__ sigma,
                    const float* __restrict__ pow_p,
                    const float* __restrict__ ker,
                    const float* __restrict__ weight,
                    const float* __restrict__ bias,
                    float* __restrict__ out)
{
    extern __shared__ float sh[];   // swizzled xp plane
    const int plane = blockIdx.x;          // b*C + c
    const int c = plane & (NCH - 1);
    const float* __restrict__ xin = x + (size_t)plane * NP;
    float* __restrict__ po = out + (size_t)plane * NP;

    const float p  = pow_p[c];
    const bool  p2 = (p == 2.0f);

    // ---- Phase 1: coalesced scalar load + x^p -> swizzled shared ----
    // consecutive lanes -> consecutive banks: conflict-free STS
#pragma unroll 4
    for (int i = threadIdx.x; i < NP; i += 256) {
        float v = xin[i];
        float r = p2 ? v * v : __powf(v, p);
        int y = i / Ww;
        int xx = i - y * Ww;
        sh[saddr(y, xx)] = r;
    }

    // per-channel params in registers
    float kc[25];
#pragma unroll
    for (int i = 0; i < 25; i++) kc[i] = __ldg(&ker[c * 25 + i]);
    const float sgm = sigma[c];
    const float sp  = p2 ? sgm * sgm : __powf(sgm, p);
    const float wgt = weight[c];
    const float bs  = bias[c];

    __syncthreads();

    // ---- Phase 2: 8-wide x 2-tall tiles (14 x-groups, 56 row-pairs) ----
    // lane stride is 2 rows; the (y>>5)&1 swizzle keeps LDS conflict-free.
    for (int idx = threadIdx.x; idx < 14 * 56; idx += 256) {
        const int xg = idx / 56;
        const int yp = idx - xg * 56;
        const int y0 = yp << 1;
        const int x0 = xg << 3;
        const int c0 = min(max(y0, 2), 109);
        const int c1 = min(max(y0 + 1, 2), 109);
        const bool two = (c1 != c0);        // false only for row pairs (0,1),(110,111)
        const int ybase = c0 - 2;
        const int bx = min(max(x0 - 2, 0), 100);

        float acc0[8], acc1[8];
#pragma unroll
        for (int j = 0; j < 8; j++) { acc0[j] = 0.0f; acc1[j] = 0.0f; }

        if (xg == 0)
            conv8x2<0,0,0,1,2,3,4,5>(sh, ybase, bx, kc, acc0, acc1, two);
        else if (xg == 13)
            conv8x2<2,3,4,5,6,7,7,7>(sh, ybase, bx, kc, acc0, acc1, two);
        else
            conv8x2<0,1,2,3,4,5,6,7>(sh, ybase, bx, kc, acc0, acc1, two);

        if (!two) {
#pragma unroll
            for (int j = 0; j < 8; j++) acc1[j] = acc0[j];
        }

        // normalize + vectorized stores (two float4 per row)
#pragma unroll
        for (int rr = 0; rr < 2; rr++) {
            const int y = y0 + rr;
            const float* xr = sh + saddr(y, x0);
            const float* acc = rr ? acc1 : acc0;
            float4 o0, o1;
            o0.x = __fdividef(wgt * xr[0], sp + acc[0]) + bs;
            o0.y = __fdividef(wgt * xr[1], sp + acc[1]) + bs;
            o0.z = __fdividef(wgt * xr[2], sp + acc[2]) + bs;
            o0.w = __fdividef(wgt * xr[3], sp + acc[3]) + bs;
            o1.x = __fdividef(wgt * xr[4], sp + acc[4]) + bs;
            o1.y = __fdividef(wgt * xr[5], sp + acc[5]) + bs;
            o1.z = __fdividef(wgt * xr[6], sp + acc[6]) + bs;
            o1.w = __fdividef(wgt * xr[7], sp + acc[7]) + bs;
            float4* orow = reinterpret_cast<float4*>(po + y * Ww + x0);
            orow[0] = o0;
            orow[1] = o1;
        }
    }
}

extern "C" void kernel_launch(void* const* d_in, const int* in_sizes, int n_in,
                              void* d_out, int out_size)
{
    const float* x      = (const float*)d_in[0];
    const float* sigma  = (const float*)d_in[1];
    const float* pow_p  = (const float*)d_in[2];
    const float* ker    = (const float*)d_in[3];
    const float* weight = (const float*)d_in[4];
    const float* bias   = (const float*)d_in[5];
    float* out = (float*)d_out;

    cudaFuncSetAttribute(bionorm_kernel,
                         cudaFuncAttributeMaxDynamicSharedMemorySize,
                         SMEM_BYTES);

    bionorm_kernel<<<32 * NCH, 256, SMEM_BYTES>>>(x, sigma, pow_p, ker,
                                                  weight, bias, out);
}

// round 3
// speedup vs baseline: 1.8173x; 1.2862x over previous
#include <cuda_runtime.h>

#define Ww 112
#define Hh 112
#define NP (Hh*Ww)          // 12544 floats per plane
#define NCH 64
#define RSTR 32             // shared row stride in float4 units (128 floats)
#define NROWS_MAX 60

// fma a float4-lane k (absolute col index in 16-float window) into tv[k-TLO]
#define VACC(K, VAL)                                                  \
    if constexpr ((K) >= TLO && (K) < TLO + 12) {                     \
        tv[(K) - TLO] = fmaf(w, (VAL), tv[(K) - TLO]);                \
    }

__device__ __forceinline__ void loadrow16(const float4* __restrict__ s4,
                                          int ly, int gb, float* __restrict__ rv)
{
    const int sw = ly & 7;
    const float4* rp = s4 + ly * RSTR;
    float4 a = rp[(gb + 0) ^ sw];
    float4 b = rp[(gb + 1) ^ sw];
    float4 c = rp[(gb + 2) ^ sw];
    float4 d = rp[(gb + 3) ^ sw];
    rv[0]=a.x;  rv[1]=a.y;  rv[2]=a.z;  rv[3]=a.w;
    rv[4]=b.x;  rv[5]=b.y;  rv[6]=b.z;  rv[7]=b.w;
    rv[8]=c.x;  rv[9]=c.y;  rv[10]=c.z; rv[11]=c.w;
    rv[12]=d.x; rv[13]=d.y; rv[14]=d.z; rv[15]=d.w;
}

// 8-wide, 1-row output tile. Window = 16 floats starting at float4-group gb.
// TLO: first window column actually needed; offr[j]: per-output window start
// relative to TLO. Separable path: vertical pass (rk) into tv[12], then
// horizontal pass (ck). Fallback: direct 25-tap conv, coeffs via __ldg.
template<int TLO,int O0,int O1,int O2,int O3,int O4,int O5,int O6,int O7>
__device__ __forceinline__ void conv8(const float4* __restrict__ s4,
                                      int lybase, int gb,
                                      const float* __restrict__ rk,
                                      const float* __restrict__ ck,
                                      bool sep,
                                      const float* __restrict__ kerg,
                                      float* __restrict__ acc)
{
    const int offr[8] = {O0,O1,O2,O3,O4,O5,O6,O7};
    if (sep) {
        float tv[12];
#pragma unroll
        for (int i = 0; i < 12; i++) tv[i] = 0.0f;
#pragma unroll
        for (int rr = 0; rr < 5; rr++) {
            const int ly = lybase + rr;
            const int sw = ly & 7;
            const float4* rp = s4 + ly * RSTR;
            const float w = rk[rr];
            float4 q;
            q = rp[(gb + 0) ^ sw];
            VACC(0,q.x)  VACC(1,q.y)  VACC(2,q.z)  VACC(3,q.w)
            q = rp[(gb + 1) ^ sw];
            VACC(4,q.x)  VACC(5,q.y)  VACC(6,q.z)  VACC(7,q.w)
            q = rp[(gb + 2) ^ sw];
            VACC(8,q.x)  VACC(9,q.y)  VACC(10,q.z) VACC(11,q.w)
            q = rp[(gb + 3) ^ sw];
            VACC(12,q.x) VACC(13,q.y) VACC(14,q.z) VACC(15,q.w)
        }
#pragma unroll
        for (int j = 0; j < 8; j++)
#pragma unroll
            for (int t = 0; t < 5; t++)
                acc[j] = fmaf(ck[t], tv[offr[j] + t], acc[j]);
    } else {
#pragma unroll
        for (int rr = 0; rr < 5; rr++) {
            float rv[16];
            loadrow16(s4, lybase + rr, gb, rv);
#pragma unroll
            for (int t = 0; t < 5; t++) {
                const float w = __ldg(kerg + rr * 5 + t);
#pragma unroll
                for (int j = 0; j < 8; j++)
                    acc[j] = fmaf(w, rv[TLO + offr[j] + t], acc[j]);
            }
        }
    }
}

__global__ __launch_bounds__(256, 5)
void bionorm_kernel(const float* __restrict__ x,
                    const float* __restrict__ sigma,
                    const float* __restrict__ pow_p,
                    const float* __restrict__ ker,
                    const float* __restrict__ weight,
                    const float* __restrict__ bias,
                    float* __restrict__ out)
{
    __shared__ float4 s4[NROWS_MAX * RSTR];   // 30720 B, XOR-swizzled

    const int bid   = blockIdx.x;
    const int plane = bid >> 1;               // b*C + c
    const int half  = bid & 1;
    const int c     = plane & (NCH - 1);
    const int r0    = half ? 52 : 0;          // first loaded plane row
    const int nrows = half ? 60 : 58;
    const int yo0   = half * 56;              // first output row

    const float* __restrict__ xin = x + (size_t)plane * NP;
    float* __restrict__ po        = out + (size_t)plane * NP;

    const float p  = pow_p[c];
    const bool  p2 = (p == 2.0f);

    // ---- Phase 1: float4 load + x^p -> swizzled shared ----
    const float4* __restrict__ xin4 =
        reinterpret_cast<const float4*>(xin + r0 * Ww);
    const int ntot = nrows * 28;              // 28 float4 per row
    for (int i = threadIdx.x; i < ntot; i += 256) {
        const int ly = i / 28;
        const int g  = i - ly * 28;
        float4 v = xin4[ly * 28 + g];
        float4 rq;
        if (p2) {
            rq.x = v.x*v.x; rq.y = v.y*v.y; rq.z = v.z*v.z; rq.w = v.w*v.w;
        } else {
            rq.x = __powf(v.x, p); rq.y = __powf(v.y, p);
            rq.z = __powf(v.z, p); rq.w = __powf(v.w, p);
        }
        s4[ly * RSTR + (g ^ (ly & 7))] = rq;
    }

    // ---- per-channel params + runtime separability (uniform across block) ----
    const float* __restrict__ kerg = ker + c * 25;
    float kc[25];
#pragma unroll
    for (int i = 0; i < 25; i++) kc[i] = __ldg(kerg + i);

    float maxa = 0.0f;
#pragma unroll
    for (int i = 0; i < 25; i++) maxa = fmaxf(maxa, fabsf(kc[i]));
    int pi = 0; float best = -1.0f;
#pragma unroll
    for (int i = 0; i < 25; i++) {
        float a = fabsf(kc[i]);
        if (a > best) { best = a; pi = i; }
    }
    const int i0 = pi / 5, j0 = pi - (pi / 5) * 5;

    float rk[5], ck[5];
    bool sep = (maxa > 0.0f);
    if (sep) {
        const float inv = 1.0f / kc[i0 * 5 + j0];
#pragma unroll
        for (int i = 0; i < 5; i++) rk[i] = kc[i * 5 + j0] * inv;
#pragma unroll
        for (int j = 0; j < 5; j++) ck[j] = kc[i0 * 5 + j];
        const float tol = 1e-6f * maxa;
#pragma unroll
        for (int i = 0; i < 5; i++)
#pragma unroll
            for (int j = 0; j < 5; j++)
                if (fabsf(fmaf(-rk[i], ck[j], kc[i * 5 + j])) > tol) sep = false;
    } else {
#pragma unroll
        for (int i = 0; i < 5; i++) { rk[i] = 0.0f; ck[i] = 0.0f; }
    }

    const float sgm = sigma[c];
    const float sp  = p2 ? sgm * sgm : __powf(sgm, p);
    const float wgt = weight[c];
    const float bs  = bias[c];

    __syncthreads();

    // ---- Phase 2: 8-wide x 1-row tiles; lanes take consecutive rows ----
    for (int idx = threadIdx.x; idx < 14 * 56; idx += 256) {
        const int xg = idx / 56;
        const int y  = idx - xg * 56 + yo0;          // global output row
        const int cy = min(max(y, 2), 109);          // clamped conv center
        const int lybase = cy - 2 - r0;

        float acc[8];
#pragma unroll
        for (int j = 0; j < 8; j++) acc[j] = 0.0f;

        if (xg == 0)
            conv8<0, 0,0,0,1,2,3,4,5>(s4, lybase, 0,        rk, ck, sep, kerg, acc);
        else if (xg == 13)
            conv8<2, 0,1,2,3,4,5,5,5>(s4, lybase, 25,       rk, ck, sep, kerg, acc);
        else
            conv8<2, 0,1,2,3,4,5,6,7>(s4, lybase, 2*xg - 1, rk, ck, sep, kerg, acc);

        // numerator xp for this row (conflict-free: sw distinct per 8 lanes)
        const int lyy = y - r0;
        const int sw  = lyy & 7;
        const int gx  = xg << 1;
        const float4* rp = s4 + lyy * RSTR;
        const float4 n0 = rp[gx ^ sw];
        const float4 n1 = rp[(gx + 1) ^ sw];

        float4 o0, o1;
        o0.x = __fdividef(wgt * n0.x, sp + acc[0]) + bs;
        o0.y = __fdividef(wgt * n0.y, sp + acc[1]) + bs;
        o0.z = __fdividef(wgt * n0.z, sp + acc[2]) + bs;
        o0.w = __fdividef(wgt * n0.w, sp + acc[3]) + bs;
        o1.x = __fdividef(wgt * n1.x, sp + acc[4]) + bs;
        o1.y = __fdividef(wgt * n1.y, sp + acc[5]) + bs;
        o1.z = __fdividef(wgt * n1.z, sp + acc[6]) + bs;
        o1.w = __fdividef(wgt * n1.w, sp + acc[7]) + bs;

        float4* orow = reinterpret_cast<float4*>(po + y * Ww + (xg << 3));
        orow[0] = o0;
        orow[1] = o1;
    }
}

extern "C" void kernel_launch(void* const* d_in, const int* in_sizes, int n_in,
                              void* d_out, int out_size)
{
    const float* x      = (const float*)d_in[0];
    const float* sigma  = (const float*)d_in[1];
    const float* pow_p  = (const float*)d_in[2];
    const float* ker    = (const float*)d_in[3];
    const float* weight = (const float*)d_in[4];
    const float* bias   = (const float*)d_in[5];
    float* out = (float*)d_out;

    bionorm_kernel<<<32 * NCH * 2, 256>>>(x, sigma, pow_p, ker,
                                          weight, bias, out);
}